// round 6
// baseline (speedup 1.0000x reference)
#include <cuda_runtime.h>

// out[b] = -(inp[b,:] . quad)^2 + inp[b,:] . linw + bias
// B = 16384, D = 4096, fp32. 256 MiB streaming read — HBM-bound.
//
// R6 vs R5 (45.1us, DRAM 75%, regs=64): R4/R5 both pinned at 64 regs, which
// forces ptxas to reuse the x registers between rows -> effective MLP ~4 and
// a load->consume->load serial pattern. ONE change: explicit ping-pong
// prefetch (xa/xb register sets; next row's 4 LDG.128 issue before current
// row's FMAs) + __launch_bounds__(256, 3) so ~85 regs keep both sets live.
// Steady state: 4-8 independent LDG.128 in flight per warp, always.

#ifndef D_DIM
#define D_DIM 4096
#endif

constexpr int THREADS     = 256;            // 8 warps
constexpr int WARPS       = THREADS / 32;   // 8
constexpr int F4_PER_LANE = (D_DIM / WARPS) / 4 / 32;  // 4
constexpr int TILE_ROWS   = 16;
constexpr int ROW_F4      = D_DIM / 4;      // 1024 float4 per row

__global__ __launch_bounds__(THREADS, 3)
void skinny_quad_kernel(const float* __restrict__ inp,
                        const float* __restrict__ quad,
                        const float* __restrict__ linw,
                        const float* __restrict__ linb,
                        float* __restrict__ out,
                        int B)
{
    __shared__ float2 s_part[TILE_ROWS][THREADS];   // 32KB

    const int tid  = threadIdx.x;
    const int lane = tid & 31;
    const int warp = tid >> 5;
    const int cbase = warp * (D_DIM / WARPS / 4);   // warp's 128-float4 chunk

    // Weights in registers, loaded once per block
    const float4* __restrict__ gq = reinterpret_cast<const float4*>(quad) + cbase;
    const float4* __restrict__ gl = reinterpret_cast<const float4*>(linw) + cbase;
    float4 q[F4_PER_LANE], l[F4_PER_LANE];
    #pragma unroll
    for (int i = 0; i < F4_PER_LANE; ++i) {
        q[i] = gq[i * 32 + lane];
        l[i] = gl[i * 32 + lane];
    }

    const int row0 = blockIdx.x * TILE_ROWS;
    const float4* __restrict__ x0 =
        reinterpret_cast<const float4*>(inp) + (size_t)row0 * ROW_F4 + cbase;

    float4 xa[F4_PER_LANE], xb[F4_PER_LANE];

    // prologue: row 0 into xa
    #pragma unroll
    for (int i = 0; i < F4_PER_LANE; ++i)
        xa[i] = x0[i * 32 + lane];

    #pragma unroll
    for (int r = 0; r < TILE_ROWS; r += 2) {
        // prefetch row r+1 into xb BEFORE consuming xa
        {
            const float4* __restrict__ pb = x0 + (size_t)(r + 1) * ROW_F4;
            #pragma unroll
            for (int i = 0; i < F4_PER_LANE; ++i)
                xb[i] = pb[i * 32 + lane];
        }

        // compute row r from xa
        {
            float sq = 0.f, sl = 0.f;
            #pragma unroll
            for (int i = 0; i < F4_PER_LANE; ++i) {
                sq = fmaf(xa[i].x, q[i].x, sq);
                sq = fmaf(xa[i].y, q[i].y, sq);
                sq = fmaf(xa[i].z, q[i].z, sq);
                sq = fmaf(xa[i].w, q[i].w, sq);
                sl = fmaf(xa[i].x, l[i].x, sl);
                sl = fmaf(xa[i].y, l[i].y, sl);
                sl = fmaf(xa[i].z, l[i].z, sl);
                sl = fmaf(xa[i].w, l[i].w, sl);
            }
            s_part[r][tid] = make_float2(sq, sl);
        }

        // prefetch row r+2 into xa BEFORE consuming xb
        if (r + 2 < TILE_ROWS) {
            const float4* __restrict__ pa = x0 + (size_t)(r + 2) * ROW_F4;
            #pragma unroll
            for (int i = 0; i < F4_PER_LANE; ++i)
                xa[i] = pa[i * 32 + lane];
        }

        // compute row r+1 from xb
        {
            float sq = 0.f, sl = 0.f;
            #pragma unroll
            for (int i = 0; i < F4_PER_LANE; ++i) {
                sq = fmaf(xb[i].x, q[i].x, sq);
                sq = fmaf(xb[i].y, q[i].y, sq);
                sq = fmaf(xb[i].z, q[i].z, sq);
                sq = fmaf(xb[i].w, q[i].w, sq);
                sl = fmaf(xb[i].x, l[i].x, sl);
                sl = fmaf(xb[i].y, l[i].y, sl);
                sl = fmaf(xb[i].z, l[i].z, sl);
                sl = fmaf(xb[i].w, l[i].w, sl);
            }
            s_part[r + 1][tid] = make_float2(sq, sl);
        }
    }

    __syncthreads();

    // Block-wide reduction: 16 threads per row, then 4-stage shuffle.
    {
        const int row = tid >> 4;        // 0..15
        const int sub = tid & 15;        // 0..15

        float sq = 0.f, sl = 0.f;
        #pragma unroll
        for (int k = 0; k < THREADS / 16; ++k) {
            const float2 p = s_part[row][sub + k * 16];
            sq += p.x;
            sl += p.y;
        }

        #pragma unroll
        for (int off = 8; off > 0; off >>= 1) {
            sq += __shfl_down_sync(0xFFFFFFFFu, sq, off, 16);
            sl += __shfl_down_sync(0xFFFFFFFFu, sl, off, 16);
        }

        if (sub == 0) {
            const int orow = row0 + row;
            if (orow < B) {
                const float bias = *linb;
                out[orow] = fmaf(-sq, sq, sl + bias);
            }
        }
    }
}

extern "C" void kernel_launch(void* const* d_in, const int* in_sizes, int n_in,
                              void* d_out, int out_size)
{
    const float* inp  = (const float*)d_in[0];   // (B, D)
    const float* quad = (const float*)d_in[1];   // (D, 1) contiguous D floats
    const float* linw = (const float*)d_in[2];   // (1, D) contiguous D floats
    const float* linb = (const float*)d_in[3];   // (1,)
    float* out = (float*)d_out;

    const int B = in_sizes[0] / D_DIM;
    const int grid = (B + TILE_ROWS - 1) / TILE_ROWS;

    skinny_quad_kernel<<<grid, THREADS>>>(inp, quad, linw, linb, out, B);
}

// round 7
// speedup vs baseline: 1.0007x; 1.0007x over previous
#include <cuda_runtime.h>
#include <cstdint>

// out[b] = -(inp[b,:] . quad)^2 + inp[b,:] . linw + bias
// B = 16384, D = 4096, fp32. 256 MiB streaming read — HBM-bound.
//
// R7: cp.async ring. R4/R5/R6 (register LDG streaming) all plateau at 74-77%
// DRAM: loads couple to the x-register scoreboard, and warps x MLP is a
// zero-sum tradeoff. cp.async has NO destination register: loads go straight
// to smem, issue-and-forget, any depth. Each thread copies exactly the 64B
// it later consumes (copy mapping == consume mapping), so cp.async.wait_group
// alone orders producer->consumer — no __syncthreads in the streaming loop.
// 2-stage full-row ring (32KB) + 1KB partials = 33KB smem, ~4 blocks/SM.

#ifndef D_DIM
#define D_DIM 4096
#endif

constexpr int THREADS     = 256;           // 8 warps
constexpr int WARPS       = THREADS / 32;  // 8
constexpr int F4_PER_LANE = (D_DIM / WARPS) / 4 / 32;  // 4 float4/thread/row
constexpr int TILE_ROWS   = 16;
constexpr int DEPTH       = 2;             // ring stages
constexpr int ROW_BYTES   = D_DIM * 4;     // 16 KB
constexpr int STAGE_BYTES = ROW_BYTES;

__device__ __forceinline__ uint32_t smem_u32(const void* p) {
    uint32_t a;
    asm("{ .reg .u64 t; cvta.to.shared.u64 t, %1; cvt.u32.u64 %0, t; }"
        : "=r"(a) : "l"(p));
    return a;
}

__global__ __launch_bounds__(THREADS)
void skinny_quad_kernel(const float* __restrict__ inp,
                        const float* __restrict__ quad,
                        const float* __restrict__ linw,
                        const float* __restrict__ linb,
                        float* __restrict__ out,
                        int B)
{
    __shared__ __align__(16) char s_x[DEPTH * STAGE_BYTES];   // 32 KB ring
    __shared__ float2 s_part[TILE_ROWS][WARPS];               // 1 KB

    const int tid  = threadIdx.x;
    const int lane = tid & 31;
    const int warp = tid >> 5;
    const int cbase = warp * (D_DIM / WARPS / 4);   // warp's 128-float4 chunk

    // Weights in registers, loaded once per block
    const float4* __restrict__ gq = reinterpret_cast<const float4*>(quad) + cbase;
    const float4* __restrict__ gl = reinterpret_cast<const float4*>(linw) + cbase;
    float4 q[F4_PER_LANE], l[F4_PER_LANE];
    #pragma unroll
    for (int i = 0; i < F4_PER_LANE; ++i) {
        q[i] = gq[i * 32 + lane];
        l[i] = gl[i * 32 + lane];
    }

    const int row0 = blockIdx.x * TILE_ROWS;
    const char* __restrict__ gbase =
        reinterpret_cast<const char*>(inp) + (size_t)row0 * ROW_BYTES;
    const uint32_t sbase = smem_u32(s_x);

    // per-thread byte offsets within a row (the 4 float4 slots this thread
    // both copies AND consumes)
    uint32_t toff[F4_PER_LANE];
    #pragma unroll
    for (int i = 0; i < F4_PER_LANE; ++i)
        toff[i] = (uint32_t)(cbase + i * 32 + lane) * 16u;

    // ---- prologue: issue row 0 ----
    {
        const char* g = gbase;
        const uint32_t s = sbase;           // stage 0
        #pragma unroll
        for (int i = 0; i < F4_PER_LANE; ++i)
            asm volatile("cp.async.cg.shared.global [%0], [%1], 16;"
                         :: "r"(s + toff[i]), "l"(g + toff[i]));
        asm volatile("cp.async.commit_group;");
    }

    #pragma unroll 2
    for (int r = 0; r < TILE_ROWS; ++r) {
        // issue row r+1 (or an empty group to keep the count aligned)
        if (r + 1 < TILE_ROWS) {
            const char* g = gbase + (size_t)(r + 1) * ROW_BYTES;
            const uint32_t s = sbase + ((r + 1) % DEPTH) * STAGE_BYTES;
            #pragma unroll
            for (int i = 0; i < F4_PER_LANE; ++i)
                asm volatile("cp.async.cg.shared.global [%0], [%1], 16;"
                             :: "r"(s + toff[i]), "l"(g + toff[i]));
        }
        asm volatile("cp.async.commit_group;");

        // wait until at most 1 group pending -> row r's copies are complete
        asm volatile("cp.async.wait_group 1;");

        // consume stage r%DEPTH (this thread's own bytes only)
        const float4* __restrict__ xs =
            reinterpret_cast<const float4*>(s_x + (r % DEPTH) * STAGE_BYTES);

        float sq = 0.f, sl = 0.f;
        #pragma unroll
        for (int i = 0; i < F4_PER_LANE; ++i) {
            const float4 x = xs[cbase + i * 32 + lane];
            sq = fmaf(x.x, q[i].x, sq);
            sq = fmaf(x.y, q[i].y, sq);
            sq = fmaf(x.z, q[i].z, sq);
            sq = fmaf(x.w, q[i].w, sq);
            sl = fmaf(x.x, l[i].x, sl);
            sl = fmaf(x.y, l[i].y, sl);
            sl = fmaf(x.z, l[i].z, sl);
            sl = fmaf(x.w, l[i].w, sl);
        }

        // warp reduction of the (sq, sl) pair
        #pragma unroll
        for (int off = 16; off > 0; off >>= 1) {
            sq += __shfl_down_sync(0xFFFFFFFFu, sq, off);
            sl += __shfl_down_sync(0xFFFFFFFFu, sl, off);
        }
        if (lane == 0)
            s_part[r][warp] = make_float2(sq, sl);
    }

    __syncthreads();

    // Final cross-warp reduction: 8 threads per row (128 threads active)
    if (tid < TILE_ROWS * WARPS) {
        const int row = tid >> 3;        // 0..15
        const int w   = tid & 7;         // 0..7
        const float2 p = s_part[row][w];
        float sq = p.x, sl = p.y;

        #pragma unroll
        for (int off = 4; off > 0; off >>= 1) {
            sq += __shfl_down_sync(0xFFFFFFFFu, sq, off, 8);
            sl += __shfl_down_sync(0xFFFFFFFFu, sl, off, 8);
        }

        if (w == 0) {
            const int orow = row0 + row;
            if (orow < B) {
                const float bias = *linb;
                out[orow] = fmaf(-sq, sq, sl + bias);
            }
        }
    }
}

extern "C" void kernel_launch(void* const* d_in, const int* in_sizes, int n_in,
                              void* d_out, int out_size)
{
    const float* inp  = (const float*)d_in[0];   // (B, D)
    const float* quad = (const float*)d_in[1];   // (D, 1) contiguous D floats
    const float* linw = (const float*)d_in[2];   // (1, D) contiguous D floats
    const float* linb = (const float*)d_in[3];   // (1,)
    float* out = (float*)d_out;

    const int B = in_sizes[0] / D_DIM;
    const int grid = (B + TILE_ROWS - 1) / TILE_ROWS;

    skinny_quad_kernel<<<grid, THREADS>>>(inp, quad, linw, linb, out, B);
}